// round 2
// baseline (speedup 1.0000x reference)
#include <cuda_runtime.h>
#include <math.h>

// Problem constants
#define NT   65536      // N*T rows
#define DIMS 256        // D
#define MC   512        // M codes
#define BM   128        // rows per block
#define BN   128        // codes per chunk
#define BK   16         // k-chunk
#define NBLK (NT / BM)  // 512 main blocks

__device__ float g_emb_norm[MC * DIMS];
__device__ float g_e2[MC];
__device__ float g_x2[NT];
__device__ int   g_counts[MC];
__device__ float g_loss_partial[NBLK];

// ---------------------------------------------------------------------------
// Kernel 1: row-normalize codebook exactly like the reference:
//   norm = sqrt(sum(e^2)) [double-accumulated, rounded to f32]
//   ehat = e / (norm + 1e-4f)   (IEEE fp32 division, like XLA)
//   e2   = sum(ehat^2)          [double-accumulated, rounded to f32]
// Also zero the code counters.
// ---------------------------------------------------------------------------
__global__ void vq_normalize(const float* __restrict__ emb) {
    __shared__ double red[8];
    __shared__ float bcast;
    int m = blockIdx.x;        // code row
    int t = threadIdx.x;       // 256 threads = D
    float v = emb[m * DIMS + t];

    double s = (double)v * (double)v;
    #pragma unroll
    for (int o = 16; o; o >>= 1) s += __shfl_xor_sync(0xffffffffu, s, o);
    if ((t & 31) == 0) red[t >> 5] = s;
    __syncthreads();
    if (t == 0) {
        double tot = 0.0;
        #pragma unroll
        for (int i = 0; i < 8; i++) tot += red[i];
        bcast = (float)sqrt(tot);
    }
    __syncthreads();
    float norm = bcast;
    float e = v / (norm + 1e-4f);          // IEEE rn division, matches ref
    g_emb_norm[m * DIMS + t] = e;

    __syncthreads();                        // red[] reuse
    double s2 = (double)e * (double)e;
    #pragma unroll
    for (int o = 16; o; o >>= 1) s2 += __shfl_xor_sync(0xffffffffu, s2, o);
    if ((t & 31) == 0) red[t >> 5] = s2;
    __syncthreads();
    if (t == 0) {
        double tot2 = 0.0;
        #pragma unroll
        for (int i = 0; i < 8; i++) tot2 += red[i];
        g_e2[m] = (float)tot2;
        g_counts[m] = 0;
    }
}

// ---------------------------------------------------------------------------
// Kernel 1b: per-row ||x||^2, double-accumulated, rounded once to fp32.
// One warp per row; lane sums 8 strided elements (coalesced).
// ---------------------------------------------------------------------------
__global__ void vq_x2(const float* __restrict__ x) {
    int warp = (blockIdx.x * blockDim.x + threadIdx.x) >> 5;
    int lane = threadIdx.x & 31;
    if (warp >= NT) return;
    const float* row = x + (size_t)warp * DIMS;
    double s = 0.0;
    #pragma unroll
    for (int i = 0; i < 8; i++) {
        float v = __ldg(row + lane + 32 * i);
        s += (double)v * (double)v;
    }
    #pragma unroll
    for (int o = 16; o; o >>= 1) s += __shfl_xor_sync(0xffffffffu, s, o);
    if (lane == 0) g_x2[warp] = (float)s;
}

// ---------------------------------------------------------------------------
// Kernel 2: main. Per block: 128 rows. Score GEMM (128x512 over K=256) with
// 8x8 register tiles. Distance emulates the reference's fp32 arithmetic:
//   d = fl32( fl32(e2 + x2) - 2*dot )   (2*dot exact => FMA = single rounding)
// argmin with lower-index tie-break at every level. Then gather raw embedding,
// write quantized output, accumulate commitment partial, count codes.
// ---------------------------------------------------------------------------
__global__ void __launch_bounds__(256, 2)
vq_main(const float* __restrict__ x, const float* __restrict__ emb,
        float* __restrict__ out) {
    __shared__ float Xs[BK][BM + 1];
    __shared__ float Es[BK][BN + 1];
    __shared__ int   rowIdx[BM];
    __shared__ float sred[8];

    const int tid = threadIdx.x;
    const int tx = tid & 15;      // code lane (16)
    const int ty = tid >> 4;      // row lane (16)
    const int row0 = blockIdx.x * BM;

    // per-row ||x||^2 for this thread's 8 rows (broadcast loads)
    float x2r[8];
    #pragma unroll
    for (int i = 0; i < 8; i++) x2r[i] = g_x2[row0 + ty + 16 * i];

    // running best per row (valid on tx==0 threads; rows ty + 16*i)
    float bestV[8];
    int   bestI[8];
    #pragma unroll
    for (int i = 0; i < 8; i++) { bestV[i] = 3.0e38f; bestI[i] = 0x7fffffff; }

    #pragma unroll 1
    for (int nc = 0; nc < MC / BN; ++nc) {
        float acc[8][8];
        #pragma unroll
        for (int i = 0; i < 8; i++)
            #pragma unroll
            for (int j = 0; j < 8; j++) acc[i][j] = 0.f;

        #pragma unroll 1
        for (int kc = 0; kc < DIMS / BK; ++kc) {
            // load 128x16 tile of x and 128x16 tile of emb_norm
            #pragma unroll
            for (int l = 0; l < 8; l++) {
                int idx = tid + l * 256;          // 0..2047
                int m = idx >> 4;                 // 0..127
                int k = idx & 15;
                Xs[k][m] = x[(size_t)(row0 + m) * DIMS + kc * BK + k];
                Es[k][m] = g_emb_norm[(size_t)(nc * BN + m) * DIMS + kc * BK + k];
            }
            __syncthreads();
            #pragma unroll
            for (int k = 0; k < BK; k++) {
                float a[8], b[8];
                #pragma unroll
                for (int i = 0; i < 8; i++) a[i] = Xs[k][ty + 16 * i];
                #pragma unroll
                for (int j = 0; j < 8; j++) b[j] = Es[k][tx + 16 * j];
                #pragma unroll
                for (int i = 0; i < 8; i++)
                    #pragma unroll
                    for (int j = 0; j < 8; j++)
                        acc[i][j] = fmaf(a[i], b[j], acc[i][j]);
            }
            __syncthreads();
        }

        // distance epilogue with reference-identical fp32 rounding; argmin,
        // ties -> lowest index.
        #pragma unroll
        for (int i = 0; i < 8; i++) {
            float v = 3.0e38f; int bi = 0x7fffffff;
            #pragma unroll
            for (int j = 0; j < 8; j++) {
                int c = nc * BN + tx + 16 * j;
                float base = __fadd_rn(g_e2[c], x2r[i]);          // fl(e2 + x2)
                float dval = __fmaf_rn(-2.0f, acc[i][j], base);   // fl(base - 2*dot)
                if (dval < v) { v = dval; bi = c; }  // ascending c: strict < keeps lowest
            }
            // reduce over the 16 code-lanes (within half-warp)
            #pragma unroll
            for (int o = 8; o; o >>= 1) {
                float ov = __shfl_xor_sync(0xffffffffu, v, o);
                int   oi = __shfl_xor_sync(0xffffffffu, bi, o);
                if (ov < v || (ov == v && oi < bi)) { v = ov; bi = oi; }
            }
            if (tx == 0) {
                if (v < bestV[i] || (v == bestV[i] && bi < bestI[i])) {
                    bestV[i] = v; bestI[i] = bi;
                }
            }
        }
    }

    if (tx == 0) {
        #pragma unroll
        for (int i = 0; i < 8; i++) {
            rowIdx[ty + 16 * i] = bestI[i];
            atomicAdd(&g_counts[bestI[i]], 1);
        }
    }
    __syncthreads();

    // gather raw embedding rows, write quantized output, commitment partial
    float lsum = 0.f;
    #pragma unroll 4
    for (int r = 0; r < BM; r++) {
        int ci = rowIdx[r];
        float q  = emb[(size_t)ci * DIMS + tid];
        float xv = x[(size_t)(row0 + r) * DIMS + tid];
        out[(size_t)(row0 + r) * DIMS + tid] = q;
        float d = xv - q;
        lsum = fmaf(d, d, lsum);
    }
    #pragma unroll
    for (int o = 16; o; o >>= 1) lsum += __shfl_xor_sync(0xffffffffu, lsum, o);
    if ((tid & 31) == 0) sred[tid >> 5] = lsum;
    __syncthreads();
    if (tid == 0) {
        float s = 0.f;
        #pragma unroll
        for (int i = 0; i < 8; i++) s += sred[i];
        g_loss_partial[blockIdx.x] = s;
    }
}

// ---------------------------------------------------------------------------
// Kernel 3: finalize scalars. 512 threads: one per code / one per partial.
// ---------------------------------------------------------------------------
__global__ void vq_finalize(float* __restrict__ out) {
    __shared__ float sE[16], sL[16];
    int t = threadIdx.x;  // 512
    float p  = (float)g_counts[t] * (1.0f / 65536.0f);
    float ent = p * logf(p + 1e-10f);
    float lp  = g_loss_partial[t];
    #pragma unroll
    for (int o = 16; o; o >>= 1) {
        ent += __shfl_xor_sync(0xffffffffu, ent, o);
        lp  += __shfl_xor_sync(0xffffffffu, lp, o);
    }
    if ((t & 31) == 0) { sE[t >> 5] = ent; sL[t >> 5] = lp; }
    __syncthreads();
    if (t == 0) {
        float e = 0.f, l = 0.f;
        #pragma unroll
        for (int i = 0; i < 16; i++) { e += sE[i]; l += sL[i]; }
        out[(size_t)NT * DIMS]     = l * (1.0f / 16777216.0f);  // commitment mean
        out[(size_t)NT * DIMS + 1] = expf(-e);                  // perplexity
    }
}

extern "C" void kernel_launch(void* const* d_in, const int* in_sizes, int n_in,
                              void* d_out, int out_size) {
    const float* x   = (const float*)d_in[0];   // (16,4096,256)
    const float* emb = (const float*)d_in[1];   // (512,256)
    float* out = (float*)d_out;

    vq_normalize<<<MC, DIMS>>>(emb);
    vq_x2<<<NT / 8, 256>>>(x);                  // 8 warps/block, 1 warp/row
    vq_main<<<NBLK, 256>>>(x, emb, out);
    vq_finalize<<<1, MC>>>(out);
}

// round 5
// speedup vs baseline: 1.2035x; 1.2035x over previous
#include <cuda_runtime.h>
#include <cuda_bf16.h>
#include <math.h>
#include <stdint.h>

// Problem constants
#define NT   65536      // N*T rows
#define DIMS 256        // D
#define MC   512        // M codes
#define BM   128        // rows per CTA
#define CN   128        // codes per chunk
#define BK   32         // k-chunk
#define NBLK (NT / BM)  // 512 CTAs
#define PITCH 80        // smem row pitch in bytes (40 bf16) - conflict-free ldmatrix
#define SPL  (128 * PITCH)  // bytes per split tile (10240)

__device__ float g_e2[MC];
__device__ float g_x2[NT];
__device__ int   g_counts[MC];
__device__ float g_loss_partial[NBLK];
// bf16 3-way splits of the normalized codebook, K-major [MC][DIMS]
__device__ __align__(16) __nv_bfloat16 g_Eh[MC * DIMS];
__device__ __align__(16) __nv_bfloat16 g_Em[MC * DIMS];
__device__ __align__(16) __nv_bfloat16 g_El[MC * DIMS];

__device__ __forceinline__ uint32_t smem_u32(const void* p) {
    uint32_t a;
    asm("{ .reg .u64 t; cvta.to.shared.u64 t, %1; cvt.u32.u64 %0, t; }"
        : "=r"(a) : "l"(p));
    return a;
}

#define LDSM4(r0, r1, r2, r3, addr) \
    asm volatile("ldmatrix.sync.aligned.m8n8.x4.shared.b16 {%0,%1,%2,%3}, [%4];" \
                 : "=r"(r0), "=r"(r1), "=r"(r2), "=r"(r3) : "r"(addr))

#define MMA16816(d, a0, a1, a2, a3, b0, b1) \
    asm volatile("mma.sync.aligned.m16n8k16.row.col.f32.bf16.bf16.f32 " \
                 "{%0,%1,%2,%3}, {%4,%5,%6,%7}, {%8,%9}, {%0,%1,%2,%3};" \
                 : "+f"((d)[0]), "+f"((d)[1]), "+f"((d)[2]), "+f"((d)[3]) \
                 : "r"(a0), "r"(a1), "r"(a2), "r"(a3), "r"(b0), "r"(b1))

// ---------------------------------------------------------------------------
// Kernel 1: row-normalize codebook exactly like the reference; emit bf16
// 3-way splits of emb_norm; e2; zero counters.
// ---------------------------------------------------------------------------
__global__ void vq_normalize(const float* __restrict__ emb) {
    __shared__ double red[8];
    __shared__ float bcast;
    int m = blockIdx.x;
    int t = threadIdx.x;       // 256 = D
    float v = emb[m * DIMS + t];

    double s = (double)v * (double)v;
    #pragma unroll
    for (int o = 16; o; o >>= 1) s += __shfl_xor_sync(0xffffffffu, s, o);
    if ((t & 31) == 0) red[t >> 5] = s;
    __syncthreads();
    if (t == 0) {
        double tot = 0.0;
        #pragma unroll
        for (int i = 0; i < 8; i++) tot += red[i];
        bcast = (float)sqrt(tot);
    }
    __syncthreads();
    float norm = bcast;
    float e = v / (norm + 1e-4f);          // IEEE rn division, matches ref

    // 3-way bf16 split
    __nv_bfloat16 bh = __float2bfloat16_rn(e);
    float r1 = e - __bfloat162float(bh);
    __nv_bfloat16 bm = __float2bfloat16_rn(r1);
    float r2 = r1 - __bfloat162float(bm);
    __nv_bfloat16 bl = __float2bfloat16_rn(r2);
    g_Eh[m * DIMS + t] = bh;
    g_Em[m * DIMS + t] = bm;
    g_El[m * DIMS + t] = bl;

    __syncthreads();
    double s2 = (double)e * (double)e;
    #pragma unroll
    for (int o = 16; o; o >>= 1) s2 += __shfl_xor_sync(0xffffffffu, s2, o);
    if ((t & 31) == 0) red[t >> 5] = s2;
    __syncthreads();
    if (t == 0) {
        double tot2 = 0.0;
        #pragma unroll
        for (int i = 0; i < 8; i++) tot2 += red[i];
        g_e2[m] = (float)tot2;
        g_counts[m] = 0;
    }
}

// ---------------------------------------------------------------------------
// Kernel 1b: per-row ||x||^2, double-accumulated, rounded once to fp32.
// ---------------------------------------------------------------------------
__global__ void vq_x2(const float* __restrict__ x) {
    int warp = (blockIdx.x * blockDim.x + threadIdx.x) >> 5;
    int lane = threadIdx.x & 31;
    if (warp >= NT) return;
    const float* row = x + (size_t)warp * DIMS;
    double s = 0.0;
    #pragma unroll
    for (int i = 0; i < 8; i++) {
        float v = __ldg(row + lane + 32 * i);
        s += (double)v * (double)v;
    }
    #pragma unroll
    for (int o = 16; o; o >>= 1) s += __shfl_xor_sync(0xffffffffu, s, o);
    if (lane == 0) g_x2[warp] = (float)s;
}

// ---------------------------------------------------------------------------
// Kernel 2: main. 128 rows/CTA, codes in 4 chunks of 128. Split-bf16 GEMM
// (6 products) on mma.sync.m16n8k16 (baseline ISA -> HMMA tensor pipe).
// 8 warps, 2x4 layout, warp tile 64x32, register accumulators. Distance +
// argmin with reference-identical fp32 rounding; lower-index ties.
// ---------------------------------------------------------------------------
__global__ void __launch_bounds__(256, 2)
vq_main(const float* __restrict__ x, const float* __restrict__ emb,
        float* __restrict__ out) {
    extern __shared__ char dsm[];           // 6 * SPL = 61440 bytes
    __shared__ unsigned long long s_key[BM];
    __shared__ int   s_idx[BM];
    __shared__ float s_e2[MC];
    __shared__ float sred[8];

    char* As = dsm;                          // 3 A splits
    char* Bs = dsm + 3 * SPL;                // 3 B splits

    const int tid  = threadIdx.x;
    const int lane = tid & 31;
    const int w    = tid >> 5;
    const int wr   = w >> 2;                 // 0..1  (row block of 64)
    const int wc   = w & 3;                  // 0..3  (col block of 32)
    const int row0 = blockIdx.x * BM;

    if (tid < BM) s_key[tid] = 0xFFFFFFFFFFFFFFFFULL;
    s_e2[tid]       = g_e2[tid];
    s_e2[tid + 256] = g_e2[tid + 256];

    // per-thread rows: R(i,h) = wr*64 + i*16 + (lane>>2) + 8h   (q = 2i+h)
    float x2r[8];
    #pragma unroll
    for (int q = 0; q < 8; q++)
        x2r[q] = g_x2[row0 + wr * 64 + (q >> 1) * 16 + (lane >> 2) + 8 * (q & 1)];

    float bestV[8]; int bestI[8];
    #pragma unroll
    for (int q = 0; q < 8; q++) { bestV[q] = 3.0e38f; bestI[q] = 0x7fffffff; }

    const uint32_t aS = smem_u32(As), bS = smem_u32(Bs);
    // product pairs, small -> large
    const int pa[6] = {2, 0, 1, 1, 0, 0};
    const int pb[6] = {0, 2, 1, 0, 1, 0};

    #pragma unroll 1
    for (int nc = 0; nc < MC / CN; ++nc) {
        float acc[4][4][4];
        #pragma unroll
        for (int i = 0; i < 4; i++)
            #pragma unroll
            for (int j = 0; j < 4; j++)
                #pragma unroll
                for (int c = 0; c < 4; c++) acc[i][j][c] = 0.f;

        #pragma unroll 1
        for (int kc = 0; kc < DIMS / BK; ++kc) {
            // ---- A: load 128x32 fp32, split into 3 bf16 tiles
            #pragma unroll
            for (int t = 0; t < 2; ++t) {
                int v = tid + t * 256;          // 0..511
                int r = v >> 2, cg = v & 3;     // row, 8-col group
                const float* src = x + (size_t)(row0 + r) * DIMS + kc * BK + cg * 8;
                float4 f0 = *(const float4*)src;
                float4 f1 = *(const float4*)(src + 4);
                float f[8] = {f0.x, f0.y, f0.z, f0.w, f1.x, f1.y, f1.z, f1.w};
                __nv_bfloat16 h[8], m[8], l[8];
                #pragma unroll
                for (int i = 0; i < 8; i++) {
                    h[i] = __float2bfloat16_rn(f[i]);
                    float r1 = f[i] - __bfloat162float(h[i]);
                    m[i] = __float2bfloat16_rn(r1);
                    float r2 = r1 - __bfloat162float(m[i]);
                    l[i] = __float2bfloat16_rn(r2);
                }
                uint32_t off = (uint32_t)(r * PITCH + cg * 16);
                union { __nv_bfloat162 h2[4]; uint4 u; } P;
                #pragma unroll
                for (int i = 0; i < 4; i++) P.h2[i] = __halves2bfloat162(h[2*i], h[2*i+1]);
                *(uint4*)(As + off) = P.u;
                #pragma unroll
                for (int i = 0; i < 4; i++) P.h2[i] = __halves2bfloat162(m[2*i], m[2*i+1]);
                *(uint4*)(As + SPL + off) = P.u;
                #pragma unroll
                for (int i = 0; i < 4; i++) P.h2[i] = __halves2bfloat162(l[2*i], l[2*i+1]);
                *(uint4*)(As + 2 * SPL + off) = P.u;
            }
            // ---- B: 128 codes x 32 k, 3 splits (bf16, 16B vector loads)
            {
                const __nv_bfloat16* gB[3] = {g_Eh, g_Em, g_El};
                #pragma unroll
                for (int s = 0; s < 3; ++s)
                    #pragma unroll
                    for (int t = 0; t < 2; ++t) {
                        int v = tid + t * 256;
                        int r = v >> 2, cg = v & 3;
                        const uint4* src = (const uint4*)(gB[s] +
                            (size_t)(nc * CN + r) * DIMS + kc * BK + cg * 8);
                        *(uint4*)(Bs + s * SPL + r * PITCH + cg * 16) = *src;
                    }
            }
            __syncthreads();

            // ---- 6 product passes x 2 k-steps x 16 mma tiles
            #pragma unroll
            for (int p = 0; p < 6; ++p) {
                uint32_t aBase = aS + pa[p] * SPL;
                uint32_t bBase = bS + pb[p] * SPL;
                #pragma unroll
                for (int ks = 0; ks < 2; ++ks) {
                    uint32_t lsw = (lane & 15) * PITCH + ks * 32 + (lane >> 4) * 16;
                    uint32_t b0, b1, b2, b3, c0, c1, c2, c3;
                    LDSM4(b0, b1, b2, b3, bBase + (wc * 32)      * PITCH + lsw);
                    LDSM4(c0, c1, c2, c3, bBase + (wc * 32 + 16) * PITCH + lsw);
                    #pragma unroll
                    for (int i = 0; i < 4; ++i) {
                        uint32_t a0, a1, a2, a3;
                        LDSM4(a0, a1, a2, a3, aBase + (wr * 64 + i * 16) * PITCH + lsw);
                        MMA16816(acc[i][0], a0, a1, a2, a3, b0, b2);
                        MMA16816(acc[i][1], a0, a1, a2, a3, b1, b3);
                        MMA16816(acc[i][2], a0, a1, a2, a3, c0, c2);
                        MMA16816(acc[i][3], a0, a1, a2, a3, c1, c3);
                    }
                }
            }
            __syncthreads();
        }

        // ---- distance + running argmin (reference-identical rounding)
        #pragma unroll
        for (int i = 0; i < 4; ++i) {
            #pragma unroll
            for (int h = 0; h < 2; ++h) {
                int q = 2 * i + h;
                float bv = bestV[q]; int bi = bestI[q];
                #pragma unroll
                for (int j = 0; j < 4; ++j) {
                    #pragma unroll
                    for (int cl = 0; cl < 2; ++cl) {
                        int c = nc * CN + wc * 32 + j * 8 + 2 * (lane & 3) + cl;
                        float base = __fadd_rn(s_e2[c], x2r[q]);
                        float dval = __fmaf_rn(-2.0f, acc[i][j][2 * h + cl], base);
                        if (dval < bv) { bv = dval; bi = c; }  // asc c: keeps lowest
                    }
                }
                bestV[q] = bv; bestI[q] = bi;
            }
        }
    }

    // ---- cross-warp/lane argmin via packed atomicMin (v asc, then idx asc)
    #pragma unroll
    for (int q = 0; q < 8; ++q) {
        int row = wr * 64 + (q >> 1) * 16 + (lane >> 2) + 8 * (q & 1);
        uint32_t u = __float_as_uint(bestV[q]);
        uint32_t k = (u & 0x80000000u) ? ~u : (u | 0x80000000u);
        unsigned long long key = ((unsigned long long)k << 32) | (uint32_t)bestI[q];
        atomicMin(&s_key[row], key);
    }
    __syncthreads();
    if (tid < BM) {
        int bi = (int)(uint32_t)s_key[tid];
        s_idx[tid] = bi;
        atomicAdd(&g_counts[bi], 1);
    }
    __syncthreads();

    // ---- gather raw embedding rows, write out, commitment partial
    float lsum = 0.f;
    #pragma unroll 4
    for (int r = 0; r < BM; r++) {
        int ci = s_idx[r];
        float qv = emb[(size_t)ci * DIMS + tid];
        float xv = x[(size_t)(row0 + r) * DIMS + tid];
        out[(size_t)(row0 + r) * DIMS + tid] = qv;
        float d = xv - qv;
        lsum = fmaf(d, d, lsum);
    }
    #pragma unroll
    for (int o = 16; o; o >>= 1) lsum += __shfl_xor_sync(0xffffffffu, lsum, o);
    if ((tid & 31) == 0) sred[tid >> 5] = lsum;
    __syncthreads();
    if (tid == 0) {
        float s = 0.f;
        #pragma unroll
        for (int i = 0; i < 8; i++) s += sred[i];
        g_loss_partial[blockIdx.x] = s;
    }
}

// ---------------------------------------------------------------------------
// Kernel 3: finalize scalars.
// ---------------------------------------------------------------------------
__global__ void vq_finalize(float* __restrict__ out) {
    __shared__ float sE[16], sL[16];
    int t = threadIdx.x;  // 512
    float p  = (float)g_counts[t] * (1.0f / 65536.0f);
    float ent = p * logf(p + 1e-10f);
    float lp  = g_loss_partial[t];
    #pragma unroll
    for (int o = 16; o; o >>= 1) {
        ent += __shfl_xor_sync(0xffffffffu, ent, o);
        lp  += __shfl_xor_sync(0xffffffffu, lp, o);
    }
    if ((t & 31) == 0) { sE[t >> 5] = ent; sL[t >> 5] = lp; }
    __syncthreads();
    if (t == 0) {
        float e = 0.f, l = 0.f;
        #pragma unroll
        for (int i = 0; i < 16; i++) { e += sE[i]; l += sL[i]; }
        out[(size_t)NT * DIMS]     = l * (1.0f / 16777216.0f);
        out[(size_t)NT * DIMS + 1] = expf(-e);
    }
}

extern "C" void kernel_launch(void* const* d_in, const int* in_sizes, int n_in,
                              void* d_out, int out_size) {
    const float* x   = (const float*)d_in[0];   // (16,4096,256)
    const float* emb = (const float*)d_in[1];   // (512,256)
    float* out = (float*)d_out;

    static int attr_done = 0;
    const int DSMEM = 6 * SPL;                  // 61440 bytes
    if (!attr_done) {
        cudaFuncSetAttribute(vq_main, cudaFuncAttributeMaxDynamicSharedMemorySize, DSMEM);
        attr_done = 1;
    }

    vq_normalize<<<MC, DIMS>>>(emb);
    vq_x2<<<NT / 8, 256>>>(x);
    vq_main<<<NBLK, 256, DSMEM>>>(x, emb, out);
    vq_finalize<<<1, MC>>>(out);
}

// round 6
// speedup vs baseline: 2.0120x; 1.6718x over previous
#include <cuda_runtime.h>
#include <cuda_fp16.h>
#include <math.h>
#include <stdint.h>

// Problem constants
#define NT   65536      // N*T rows
#define DIMS 256        // D
#define MC   512        // M codes
#define BM   128        // rows per CTA
#define CN   128        // codes per chunk
#define BK   32         // k-chunk
#define NBLK (NT / BM)  // 512 CTAs
#define PITCH 80        // smem row pitch bytes (conflict-free ldmatrix)
#define TILE (128 * PITCH)      // 10240 bytes per 128x32 fp16 tile
#define STAGE (4 * TILE)        // Ah, Al, Bh, Bl per stage

__device__ float g_e2[MC];
__device__ float g_x2[NT];
__device__ int   g_counts[MC];
__device__ float g_loss_partial[NBLK];
// fp16 2-way splits (hi + lo), K-major
__device__ __align__(16) __half g_Eh[MC * DIMS];
__device__ __align__(16) __half g_El[MC * DIMS];
__device__ __align__(16) __half g_Xh[NT * DIMS];
__device__ __align__(16) __half g_Xl[NT * DIMS];

__device__ __forceinline__ uint32_t smem_u32(const void* p) {
    uint32_t a;
    asm("{ .reg .u64 t; cvta.to.shared.u64 t, %1; cvt.u32.u64 %0, t; }"
        : "=r"(a) : "l"(p));
    return a;
}

#define LDSM4(r0, r1, r2, r3, addr) \
    asm volatile("ldmatrix.sync.aligned.m8n8.x4.shared.b16 {%0,%1,%2,%3}, [%4];" \
                 : "=r"(r0), "=r"(r1), "=r"(r2), "=r"(r3) : "r"(addr))

#define MMA16816(d, a0, a1, a2, a3, b0, b1) \
    asm volatile("mma.sync.aligned.m16n8k16.row.col.f32.f16.f16.f32 " \
                 "{%0,%1,%2,%3}, {%4,%5,%6,%7}, {%8,%9}, {%0,%1,%2,%3};" \
                 : "+f"((d)[0]), "+f"((d)[1]), "+f"((d)[2]), "+f"((d)[3]) \
                 : "r"(a0), "r"(a1), "r"(a2), "r"(a3), "r"(b0), "r"(b1))

#define CP_ASYNC16(dst, src) \
    asm volatile("cp.async.cg.shared.global [%0], [%1], 16;" \
                 :: "r"(dst), "l"(src) : "memory")
#define CP_COMMIT() asm volatile("cp.async.commit_group;" ::: "memory")
#define CP_WAIT(n)  asm volatile("cp.async.wait_group %0;" :: "n"(n) : "memory")

// ---------------------------------------------------------------------------
// Kernel 1: row-normalize codebook exactly like the reference; emit fp16
// 2-way splits; e2 (double-accumulated, rounded once); zero counters.
// ---------------------------------------------------------------------------
__global__ void vq_normalize(const float* __restrict__ emb) {
    __shared__ double red[8];
    __shared__ float bcast;
    int m = blockIdx.x;
    int t = threadIdx.x;       // 256 = D
    float v = emb[m * DIMS + t];

    double s = (double)v * (double)v;
    #pragma unroll
    for (int o = 16; o; o >>= 1) s += __shfl_xor_sync(0xffffffffu, s, o);
    if ((t & 31) == 0) red[t >> 5] = s;
    __syncthreads();
    if (t == 0) {
        double tot = 0.0;
        #pragma unroll
        for (int i = 0; i < 8; i++) tot += red[i];
        bcast = (float)sqrt(tot);
    }
    __syncthreads();
    float norm = bcast;
    float e = v / (norm + 1e-4f);          // IEEE rn division, matches ref

    __half h = __float2half_rn(e);
    float r1 = e - __half2float(h);
    __half l = __float2half_rn(r1);
    g_Eh[m * DIMS + t] = h;
    g_El[m * DIMS + t] = l;

    __syncthreads();
    double s2 = (double)e * (double)e;
    #pragma unroll
    for (int o = 16; o; o >>= 1) s2 += __shfl_xor_sync(0xffffffffu, s2, o);
    if ((t & 31) == 0) red[t >> 5] = s2;
    __syncthreads();
    if (t == 0) {
        double tot2 = 0.0;
        #pragma unroll
        for (int i = 0; i < 8; i++) tot2 += red[i];
        g_e2[m] = (float)tot2;
        g_counts[m] = 0;
    }
}

// ---------------------------------------------------------------------------
// Kernel 1b: per-row ||x||^2 (double-accumulated, rounded once to fp32)
// fused with the fp16 2-way split of x. One warp per row, lane = 8 contiguous.
// ---------------------------------------------------------------------------
__global__ void vq_prep_x(const float* __restrict__ x) {
    int warp = (blockIdx.x * blockDim.x + threadIdx.x) >> 5;
    int lane = threadIdx.x & 31;
    if (warp >= NT) return;
    const float* row = x + (size_t)warp * DIMS + lane * 8;
    float4 f0 = *(const float4*)row;
    float4 f1 = *(const float4*)(row + 4);
    float f[8] = {f0.x, f0.y, f0.z, f0.w, f1.x, f1.y, f1.z, f1.w};

    double s = 0.0;
    __half h[8], l[8];
    #pragma unroll
    for (int i = 0; i < 8; i++) {
        s += (double)f[i] * (double)f[i];
        h[i] = __float2half_rn(f[i]);
        float r = f[i] - __half2float(h[i]);
        l[i] = __float2half_rn(r);
    }
    union { __half2 h2[4]; uint4 u; } P;
    size_t gi = (size_t)warp * DIMS + lane * 8;
    #pragma unroll
    for (int i = 0; i < 4; i++) P.h2[i] = __halves2half2(h[2*i], h[2*i+1]);
    *(uint4*)(g_Xh + gi) = P.u;
    #pragma unroll
    for (int i = 0; i < 4; i++) P.h2[i] = __halves2half2(l[2*i], l[2*i+1]);
    *(uint4*)(g_Xl + gi) = P.u;

    #pragma unroll
    for (int o = 16; o; o >>= 1) s += __shfl_xor_sync(0xffffffffu, s, o);
    if (lane == 0) g_x2[warp] = (float)s;
}

// ---------------------------------------------------------------------------
// Kernel 2: main. 128 rows/CTA, 4 code chunks of 128. fp16 2-way split GEMM
// (3 products: hh, hl, lh) on mma.sync.m16n8k16 f16->f32, cp.async double-
// buffered. Distance + argmin with reference-identical fp32 rounding.
// ---------------------------------------------------------------------------
__global__ void __launch_bounds__(256, 2)
vq_main(const float* __restrict__ x, const float* __restrict__ emb,
        float* __restrict__ out) {
    extern __shared__ char dsm[];           // 2 * STAGE = 81920 bytes
    __shared__ unsigned long long s_key[BM];
    __shared__ int   s_idx[BM];
    __shared__ float s_e2[MC];
    __shared__ float sred[8];

    const int tid  = threadIdx.x;
    const int lane = tid & 31;
    const int w    = tid >> 5;
    const int wr   = w >> 2;                 // 0..1 (row block of 64)
    const int wc   = w & 3;                  // 0..3 (col block of 32)
    const int row0 = blockIdx.x * BM;

    if (tid < BM) s_key[tid] = 0xFFFFFFFFFFFFFFFFULL;
    s_e2[tid]       = g_e2[tid];
    s_e2[tid + 256] = g_e2[tid + 256];

    float x2r[8];
    #pragma unroll
    for (int q = 0; q < 8; q++)
        x2r[q] = g_x2[row0 + wr * 64 + (q >> 1) * 16 + (lane >> 2) + 8 * (q & 1)];

    float bestV[8]; int bestI[8];
    #pragma unroll
    for (int q = 0; q < 8; q++) { bestV[q] = 3.0e38f; bestI[q] = 0x7fffffff; }

    // cp.async task: thread covers 2 chunks per tile (r = c>>2, cg = c&3)
    const int c0 = tid, c1 = tid + 256;
    const int r_0 = c0 >> 2, cg0 = c0 & 3;
    const int r_1 = c1 >> 2, cg1 = c1 & 3;

    // issue one stage of loads: A(h,l) rows row0.., B(h,l) rows ncc*128..
    auto issue_stage = [&](int ncc, int kcc, int buf) {
        uint32_t st = smem_u32(dsm) + buf * STAGE;
        size_t ka = (size_t)kcc * BK;
        const __half* srcAh = g_Xh + (size_t)(row0) * DIMS + ka;
        const __half* srcAl = g_Xl + (size_t)(row0) * DIMS + ka;
        const __half* srcBh = g_Eh + (size_t)(ncc * CN) * DIMS + ka;
        const __half* srcBl = g_El + (size_t)(ncc * CN) * DIMS + ka;
        uint32_t d0 = (uint32_t)(r_0 * PITCH + cg0 * 16);
        uint32_t d1 = (uint32_t)(r_1 * PITCH + cg1 * 16);
        size_t s0 = (size_t)r_0 * DIMS + cg0 * 8;
        size_t s1 = (size_t)r_1 * DIMS + cg1 * 8;
        CP_ASYNC16(st + d0,            srcAh + s0);
        CP_ASYNC16(st + d1,            srcAh + s1);
        CP_ASYNC16(st + TILE + d0,     srcAl + s0);
        CP_ASYNC16(st + TILE + d1,     srcAl + s1);
        CP_ASYNC16(st + 2 * TILE + d0, srcBh + s0);
        CP_ASYNC16(st + 2 * TILE + d1, srcBh + s1);
        CP_ASYNC16(st + 3 * TILE + d0, srcBl + s0);
        CP_ASYNC16(st + 3 * TILE + d1, srcBl + s1);
        CP_COMMIT();
    };

    issue_stage(0, 0, 0);

    #pragma unroll 1
    for (int nc = 0; nc < MC / CN; ++nc) {
        float acc[4][4][4];
        #pragma unroll
        for (int i = 0; i < 4; i++)
            #pragma unroll
            for (int j = 0; j < 4; j++)
                #pragma unroll
                for (int c = 0; c < 4; c++) acc[i][j][c] = 0.f;

        #pragma unroll 1
        for (int kc = 0; kc < DIMS / BK; ++kc) {
            int step = nc * 8 + kc;
            int buf = step & 1;
            if (step < 31) {
                int ns = step + 1;
                issue_stage(ns >> 3, ns & 7, ns & 1);
                CP_WAIT(1);
            } else {
                CP_WAIT(0);
            }
            __syncthreads();

            uint32_t st = smem_u32(dsm) + buf * STAGE;
            uint32_t aH = st, aL = st + TILE;
            uint32_t bH = st + 2 * TILE, bL = st + 3 * TILE;

            #pragma unroll
            for (int ks = 0; ks < 2; ++ks) {
                uint32_t lsw = (lane & 15) * PITCH + ks * 32 + (lane >> 4) * 16;
                uint32_t bOff0 = (wc * 32) * PITCH + lsw;
                uint32_t bOff1 = (wc * 32 + 16) * PITCH + lsw;

                // --- A hi: products hh (B hi) and hl (B lo)
                uint32_t a0[4], a1[4], a2[4], a3[4];
                #pragma unroll
                for (int i = 0; i < 4; ++i)
                    LDSM4(a0[i], a1[i], a2[i], a3[i],
                          aH + (wr * 64 + i * 16) * PITCH + lsw);
                {
                    uint32_t b0, b1, b2, b3, cc0, cc1, cc2, cc3;
                    LDSM4(b0, b1, b2, b3, bL + bOff0);
                    LDSM4(cc0, cc1, cc2, cc3, bL + bOff1);
                    #pragma unroll
                    for (int i = 0; i < 4; ++i) {
                        MMA16816(acc[i][0], a0[i], a1[i], a2[i], a3[i], b0, b2);
                        MMA16816(acc[i][1], a0[i], a1[i], a2[i], a3[i], b1, b3);
                        MMA16816(acc[i][2], a0[i], a1[i], a2[i], a3[i], cc0, cc2);
                        MMA16816(acc[i][3], a0[i], a1[i], a2[i], a3[i], cc1, cc3);
                    }
                }
                uint32_t h0, h1, h2, h3, g0, g1, g2, g3;
                LDSM4(h0, h1, h2, h3, bH + bOff0);
                LDSM4(g0, g1, g2, g3, bH + bOff1);
                #pragma unroll
                for (int i = 0; i < 4; ++i) {
                    MMA16816(acc[i][0], a0[i], a1[i], a2[i], a3[i], h0, h2);
                    MMA16816(acc[i][1], a0[i], a1[i], a2[i], a3[i], h1, h3);
                    MMA16816(acc[i][2], a0[i], a1[i], a2[i], a3[i], g0, g2);
                    MMA16816(acc[i][3], a0[i], a1[i], a2[i], a3[i], g1, g3);
                }
                // --- A lo with B hi (lh)
                #pragma unroll
                for (int i = 0; i < 4; ++i) {
                    uint32_t e0, e1, e2v, e3;
                    LDSM4(e0, e1, e2v, e3, aL + (wr * 64 + i * 16) * PITCH + lsw);
                    MMA16816(acc[i][0], e0, e1, e2v, e3, h0, h2);
                    MMA16816(acc[i][1], e0, e1, e2v, e3, h1, h3);
                    MMA16816(acc[i][2], e0, e1, e2v, e3, g0, g2);
                    MMA16816(acc[i][3], e0, e1, e2v, e3, g1, g3);
                }
            }
            __syncthreads();
        }

        // ---- distance + running argmin (reference-identical rounding)
        #pragma unroll
        for (int i = 0; i < 4; ++i) {
            #pragma unroll
            for (int h = 0; h < 2; ++h) {
                int q = 2 * i + h;
                float bv = bestV[q]; int bi = bestI[q];
                #pragma unroll
                for (int j = 0; j < 4; ++j) {
                    #pragma unroll
                    for (int cl = 0; cl < 2; ++cl) {
                        int c = nc * CN + wc * 32 + j * 8 + 2 * (lane & 3) + cl;
                        float base = __fadd_rn(s_e2[c], x2r[q]);
                        float dval = __fmaf_rn(-2.0f, acc[i][j][2 * h + cl], base);
                        if (dval < bv) { bv = dval; bi = c; }  // asc c: keeps lowest
                    }
                }
                bestV[q] = bv; bestI[q] = bi;
            }
        }
    }

    // ---- cross-warp/lane argmin via packed atomicMin (v asc, then idx asc)
    #pragma unroll
    for (int q = 0; q < 8; ++q) {
        int row = wr * 64 + (q >> 1) * 16 + (lane >> 2) + 8 * (q & 1);
        uint32_t u = __float_as_uint(bestV[q]);
        uint32_t k = (u & 0x80000000u) ? ~u : (u | 0x80000000u);
        unsigned long long key = ((unsigned long long)k << 32) | (uint32_t)bestI[q];
        atomicMin(&s_key[row], key);
    }
    __syncthreads();
    if (tid < BM) {
        int bi = (int)(uint32_t)s_key[tid];
        s_idx[tid] = bi;
        atomicAdd(&g_counts[bi], 1);
    }
    __syncthreads();

    // ---- gather raw embedding rows, write out, commitment partial
    float lsum = 0.f;
    #pragma unroll 4
    for (int r = 0; r < BM; r++) {
        int ci = s_idx[r];
        float qv = emb[(size_t)ci * DIMS + tid];
        float xv = x[(size_t)(row0 + r) * DIMS + tid];
        out[(size_t)(row0 + r) * DIMS + tid] = qv;
        float d = xv - qv;
        lsum = fmaf(d, d, lsum);
    }
    #pragma unroll
    for (int o = 16; o; o >>= 1) lsum += __shfl_xor_sync(0xffffffffu, lsum, o);
    if ((tid & 31) == 0) sred[tid >> 5] = lsum;
    __syncthreads();
    if (tid == 0) {
        float s = 0.f;
        #pragma unroll
        for (int i = 0; i < 8; i++) s += sred[i];
        g_loss_partial[blockIdx.x] = s;
    }
}

// ---------------------------------------------------------------------------
// Kernel 3: finalize scalars.
// ---------------------------------------------------------------------------
__global__ void vq_finalize(float* __restrict__ out) {
    __shared__ float sE[16], sL[16];
    int t = threadIdx.x;  // 512
    float p  = (float)g_counts[t] * (1.0f / 65536.0f);
    float ent = p * logf(p + 1e-10f);
    float lp  = g_loss_partial[t];
    #pragma unroll
    for (int o = 16; o; o >>= 1) {
        ent += __shfl_xor_sync(0xffffffffu, ent, o);
        lp  += __shfl_xor_sync(0xffffffffu, lp, o);
    }
    if ((t & 31) == 0) { sE[t >> 5] = ent; sL[t >> 5] = lp; }
    __syncthreads();
    if (t == 0) {
        float e = 0.f, l = 0.f;
        #pragma unroll
        for (int i = 0; i < 16; i++) { e += sE[i]; l += sL[i]; }
        out[(size_t)NT * DIMS]     = l * (1.0f / 16777216.0f);
        out[(size_t)NT * DIMS + 1] = expf(-e);
    }
}

extern "C" void kernel_launch(void* const* d_in, const int* in_sizes, int n_in,
                              void* d_out, int out_size) {
    const float* x   = (const float*)d_in[0];   // (16,4096,256)
    const float* emb = (const float*)d_in[1];   // (512,256)
    float* out = (float*)d_out;

    static int attr_done = 0;
    const int DSMEM = 2 * STAGE;                // 81920 bytes
    if (!attr_done) {
        cudaFuncSetAttribute(vq_main, cudaFuncAttributeMaxDynamicSharedMemorySize, DSMEM);
        attr_done = 1;
    }

    vq_normalize<<<MC, DIMS>>>(emb);
    vq_prep_x<<<NT / 8, 256>>>(x);              // 8 warps/block, 1 warp/row
    vq_main<<<NBLK, 256, DSMEM>>>(x, emb, out);
    vq_finalize<<<1, MC>>>(out);
}